// round 9
// baseline (speedup 1.0000x reference)
#include <cuda_runtime.h>

// CLUBv2: mi = BETA * sum_d Var_d(y[:, d])
// y: [1024, 256] fp32 row-major. Output: 1 fp32 scalar.
//
//   mi = ( (sum_all y^2)/N - sum_d mu_d^2 ) * BETA
//
// GRID=8 x 1024 threads: fewest ticket arrivals / least cross-SM skew.
// float4 loads (8x LDG.128/thread), per-block smem combine so each column
// emits ONE disjoint plain store per block (8KB of partials total).
// One acq_rel ticket per block; winner reduces in fixed order ->
// bit-deterministic fp32. No data atomics (R5/R6 lesson).

#define N_ROWS 1024
#define N_COLS 256
#define GRID   8
#define THREADS 1024
#define ROWS_PER_BLOCK (N_ROWS / GRID)      // 128
#define PHASES 16                           // row-phases per block
#define BETA_F 0.001f

__device__ float        g_ps[GRID * N_COLS];  // per-block column sums (8KB)
__device__ float        g_qp[GRID * 32];      // per-warp sumsq (1KB)
__device__ unsigned int g_ticket = 0;
// g_ps/g_qp fully overwritten every launch; winner resets g_ticket ->
// every graph replay identical. Deterministic.

__device__ __forceinline__ unsigned int atom_add_acq_rel(unsigned int* addr,
                                                         unsigned int v) {
    unsigned int old;
    asm volatile("atom.acq_rel.gpu.global.add.u32 %0, [%1], %2;"
                 : "=r"(old) : "l"(addr), "r"(v) : "memory");
    return old;
}

__global__ void __launch_bounds__(THREADS, 1)
club_var_kernel(const float* __restrict__ y, float* __restrict__ out) {
    const int t    = threadIdx.x;
    const int b    = blockIdx.x;
    const int lane = t & 31;
    const int warp = t >> 5;

    __shared__ float4 sm_s[PHASES * 64];   // 16KB: [rp*64 + quad]
    __shared__ float  wsum[8];
    __shared__ bool   is_last;

    // Phase 1: thread (quad, rp) covers rows rp + 16*i (i=0..7) of this
    // block's 128-row slice, columns 4*quad..4*quad+3. 8x LDG.128,
    // fully coalesced (warp = contiguous 512B).
    const int quad = t & 63;     // 0..63
    const int rp   = t >> 6;     // 0..15
    const float4* p = (const float4*)y
                    + ((size_t)(b * ROWS_PER_BLOCK + rp) * (N_COLS / 4)) + quad;

    float4 s4 = make_float4(0.f, 0.f, 0.f, 0.f);
    float  q  = 0.0f;
    #pragma unroll
    for (int i = 0; i < 8; ++i) {
        float4 v = p[i * PHASES * (N_COLS / 4)];   // +16 rows per step
        s4.x += v.x; s4.y += v.y; s4.z += v.z; s4.w += v.w;
        q = fmaf(v.x, v.x, q);
        q = fmaf(v.y, v.y, q);
        q = fmaf(v.z, v.z, q);
        q = fmaf(v.w, v.w, q);
    }

    // Q: warp shuffle-reduce (fixed order); per-warp disjoint store.
    #pragma unroll
    for (int off = 16; off > 0; off >>= 1)
        q += __shfl_down_sync(0xFFFFFFFFu, q, off);
    if (lane == 0) __stcg(&g_qp[b * 32 + warp], q);

    // Combine 16 row-phase partials per column in smem -> ONE store per
    // column per block. LDS pattern is bank-conflict-free (lanes span
    // 32 consecutive floats per phase).
    sm_s[rp * 64 + quad] = s4;
    __syncthreads();

    if (t < N_COLS) {
        const float* smf = (const float*)sm_s;   // smf[ph*256 + col]
        // Fixed-order pairwise sum over 16 phases -> deterministic.
        float p0 = (smf[0*256+t] + smf[1*256+t]) + (smf[2*256+t] + smf[3*256+t]);
        float p1 = (smf[4*256+t] + smf[5*256+t]) + (smf[6*256+t] + smf[7*256+t]);
        float p2 = (smf[8*256+t] + smf[9*256+t]) + (smf[10*256+t] + smf[11*256+t]);
        float p3 = (smf[12*256+t] + smf[13*256+t]) + (smf[14*256+t] + smf[15*256+t]);
        __stcg(&g_ps[b * N_COLS + t], (p0 + p1) + (p2 + p3));
    }

    // Ticket: bar.sync orders this block's stores before t0's gpu-scope
    // acq_rel release; only 8 arrivals total.
    __syncthreads();
    if (t == 0)
        is_last = (atom_add_acq_rel(&g_ticket, 1u) == (unsigned)(GRID - 1));
    __syncthreads();

    if (is_last) {
        float acc = 0.0f, qv = 0.0f;
        if (t < N_COLS) {
            // Tail: 8KB coalesced. Thread t sums column t over 8 blocks.
            float a0 = (__ldcg(&g_ps[0 * N_COLS + t]) + __ldcg(&g_ps[1 * N_COLS + t]))
                     + (__ldcg(&g_ps[2 * N_COLS + t]) + __ldcg(&g_ps[3 * N_COLS + t]));
            float a1 = (__ldcg(&g_ps[4 * N_COLS + t]) + __ldcg(&g_ps[5 * N_COLS + t]))
                     + (__ldcg(&g_ps[6 * N_COLS + t]) + __ldcg(&g_ps[7 * N_COLS + t]));
            const float mu = (a0 + a1) * (1.0f / (float)N_ROWS);
            acc = mu * mu;

            // Warp 0 also picks up the 256 Q partials (2x LDG.128/lane).
            if (warp == 0) {
                const float4* qp = (const float4*)g_qp;
                float4 q0 = __ldcg(&qp[2 * lane + 0]);
                float4 q1 = __ldcg(&qp[2 * lane + 1]);
                qv = ((q0.x + q0.y) + (q0.z + q0.w))
                   + ((q1.x + q1.y) + (q1.z + q1.w));
            }

            // Fixed-order reduction of sum_d mu_d^2 (warps 0..7).
            #pragma unroll
            for (int off = 16; off > 0; off >>= 1)
                acc += __shfl_down_sync(0xFFFFFFFFu, acc, off);
            if (lane == 0) wsum[warp] = acc;
        }
        __syncthreads();

        if (warp == 0) {
            #pragma unroll
            for (int off = 16; off > 0; off >>= 1)
                qv += __shfl_down_sync(0xFFFFFFFFu, qv, off);

            float v = (lane < 8) ? wsum[lane] : 0.0f;
            #pragma unroll
            for (int off = 4; off > 0; off >>= 1)
                v += __shfl_down_sync(0xFFFFFFFFu, v, off);

            if (lane == 0) {
                const float EQ = qv * (1.0f / (float)N_ROWS); // sum_d E[y^2]_d
                out[0] = (EQ - v) * BETA_F;
                g_ticket = 0;   // reset for next graph replay
            }
        }
    }
}

extern "C" void kernel_launch(void* const* d_in, const int* in_sizes, int n_in,
                              void* d_out, int out_size) {
    (void)in_sizes; (void)n_in; (void)out_size;
    const float* y = (const float*)d_in[0];
    float* out = (float*)d_out;
    club_var_kernel<<<GRID, THREADS>>>(y, out);
}

// round 10
// speedup vs baseline: 1.3478x; 1.3478x over previous
#include <cuda_runtime.h>

// CLUBv2: mi = BETA * sum_d Var_d(y[:, d])
// y: [1024, 256] fp32 row-major. Output: 1 fp32 scalar.
//
//   mi = ( (sum_all y^2)/N - sum_d mu_d^2 ) * BETA
//
// Champion structure (R7, best measured): GRID=32 x 256, coalesced scalar
// loads, disjoint per-block plain stores (no data atomics — R5/R6 showed
// L2 atomic-ALU drain dominates), ONE acq_rel ticket per block, winner
// block reduces 32KB in fixed order -> bit-deterministic fp32.
// R10 delta: tail S-sum uses 4 independent accumulators (shorter chain).

#define N_ROWS 1024
#define N_COLS 256
#define GRID   32
#define ROWS_PER_BLOCK (N_ROWS / GRID)   // 32
#define BETA_F 0.001f

__device__ float        g_ps[GRID * N_COLS];  // per-block column sums (32KB)
__device__ float        g_qp[GRID];           // per-block sum-of-squares
__device__ unsigned int g_ticket = 0;
// g_ps/g_qp fully overwritten every launch; winner resets g_ticket ->
// every graph replay identical. Deterministic.

__device__ __forceinline__ unsigned int atom_add_acq_rel(unsigned int* addr,
                                                         unsigned int v) {
    unsigned int old;
    asm volatile("atom.acq_rel.gpu.global.add.u32 %0, [%1], %2;"
                 : "=r"(old) : "l"(addr), "r"(v) : "memory");
    return old;
}

__global__ void __launch_bounds__(N_COLS, 1)
club_var_kernel(const float* __restrict__ y, float* __restrict__ out) {
    const int t    = threadIdx.x;   // column index 0..255
    const int b    = blockIdx.x;
    const int lane = t & 31;
    const int warp = t >> 5;

    // Phase 1: 32 rows per block per column, coalesced scalar loads,
    // fully unrolled -> deep MLP, one memory-latency exposure.
    float s = 0.0f, q = 0.0f;
    const float* p = y + (size_t)b * ROWS_PER_BLOCK * N_COLS + t;
    #pragma unroll
    for (int r = 0; r < ROWS_PER_BLOCK; ++r) {
        float v = p[r * N_COLS];
        s += v;
        q = fmaf(v, v, q);
    }

    // Per-block column partial: ONE plain store, disjoint slot.
    __stcg(&g_ps[b * N_COLS + t], s);

    // Q: warp shuffle-reduce (fixed order), 8 partials through smem.
    #pragma unroll
    for (int off = 16; off > 0; off >>= 1)
        q += __shfl_down_sync(0xFFFFFFFFu, q, off);
    __shared__ float sm_q[8];
    __shared__ bool  is_last;
    if (lane == 0) sm_q[warp] = q;

    // Ticket: bar.sync orders all stores intra-block; t0 stores the block's
    // Q partial, then its gpu-scope acq_rel release publishes everything.
    __syncthreads();
    if (t == 0) {
        float qb = ((sm_q[0] + sm_q[1]) + (sm_q[2] + sm_q[3]))
                 + ((sm_q[4] + sm_q[5]) + (sm_q[6] + sm_q[7]));
        __stcg(&g_qp[b], qb);
        is_last = (atom_add_acq_rel(&g_ticket, 1u) == (unsigned)(GRID - 1));
    }
    __syncthreads();

    if (is_last) {
        // Tail: 32KB from L2, coalesced (warp instr = 1 x 128B line).
        // Thread t sums column t across 32 blocks: 4 independent
        // accumulators (max serial chain 8), fixed order -> deterministic.
        float a0 = 0.f, a1 = 0.f, a2 = 0.f, a3 = 0.f;
        #pragma unroll
        for (int bb = 0; bb < GRID; bb += 4) {
            a0 += __ldcg(&g_ps[(bb + 0) * N_COLS + t]);
            a1 += __ldcg(&g_ps[(bb + 1) * N_COLS + t]);
            a2 += __ldcg(&g_ps[(bb + 2) * N_COLS + t]);
            a3 += __ldcg(&g_ps[(bb + 3) * N_COLS + t]);
        }
        const float S = (a0 + a1) + (a2 + a3);

        // Warp 0 picks up the 32 Q partials in parallel (independent path).
        float qv = 0.0f;
        if (warp == 0) qv = __ldcg(&g_qp[lane]);

        const float mu = S * (1.0f / (float)N_ROWS);
        float acc = mu * mu;                 // this thread's mu_d^2

        // Fixed-order reduction of sum_d mu_d^2.
        #pragma unroll
        for (int off = 16; off > 0; off >>= 1)
            acc += __shfl_down_sync(0xFFFFFFFFu, acc, off);
        __shared__ float wsum[8];
        if (lane == 0) wsum[warp] = acc;
        __syncthreads();

        if (warp == 0) {
            // Qtot: fixed-order shuffle tree over the 32 partials.
            #pragma unroll
            for (int off = 16; off > 0; off >>= 1)
                qv += __shfl_down_sync(0xFFFFFFFFu, qv, off);

            float v = (lane < 8) ? wsum[lane] : 0.0f;
            #pragma unroll
            for (int off = 4; off > 0; off >>= 1)
                v += __shfl_down_sync(0xFFFFFFFFu, v, off);

            if (lane == 0) {
                const float EQ = qv * (1.0f / (float)N_ROWS); // sum_d E[y^2]_d
                out[0] = (EQ - v) * BETA_F;
                g_ticket = 0;   // reset for next graph replay
            }
        }
    }
}

extern "C" void kernel_launch(void* const* d_in, const int* in_sizes, int n_in,
                              void* d_out, int out_size) {
    (void)in_sizes; (void)n_in; (void)out_size;
    const float* y = (const float*)d_in[0];
    float* out = (float*)d_out;
    club_var_kernel<<<GRID, N_COLS>>>(y, out);
}